// round 12
// baseline (speedup 1.0000x reference)
#include <cuda_runtime.h>
#include <cuda_bf16.h>
#include <math.h>

// EMLTree1DLinear — planar output (PROVEN), 4-threads-per-element tree split.
// R11 (2 threads/elem): 187.5us, occ 35%, issue 78% -> still latency-bound;
// MUFU floor ~105us. Quarter-trees (256 leaves, height-8) per thread, then
// two redundant shuffle merges: h=8 (gate 1020 + (t>>1)) and root h=9 (gate
// 1022). Total param-LDG and MUFU work is conserved; occupancy doubles again.
// Dataflow per merge is bit-identical to the R9/R11 passing kernels.

#define N_LEAVES   1024
#define N_INTERNAL 1023
#define CLAMP_F    1000000.0f
#define PI_F       3.14159265358979323846f
#define PI_2_F     1.57079632679489661923f

struct C2 { float re, im; };

__device__ __forceinline__ float san1(float v) {
    return (v != v) ? 0.0f : fminf(fmaxf(v, -CLAMP_F), CLAMP_F);
}

// sanitize(cexp(A*B)) — strict _rn complex mul keeps signed zeros / inf*0=NaN
__device__ __forceinline__ C2 cexp_mul_san(float Ar, float Ai, float Br, float Bi) {
    float mr = __fsub_rn(__fmul_rn(Ar, Br), __fmul_rn(Ai, Bi));
    float mi = __fadd_rn(__fmul_rn(Ar, Bi), __fmul_rn(Ai, Br));
    float e = __expf(mr);
    float s, c;
    __sincosf(mi, &s, &c);
    C2 w;
    w.re = san1(__fmul_rn(e, c));
    w.im = san1(__fmul_rn(e, s));
    return w;
}

// complex log, branch-cut exact (PROVEN): Lr = log|z| scaled-hypot,
// Li = atan2(im, re) via shared divide + deg-11 minimax.
__device__ __forceinline__ C2 fast_clog(C2 z) {
    float ax = fabsf(z.re), ay = fabsf(z.im);
    float mx = fmaxf(ax, ay);
    float mn = fminf(ax, ay);
    float t  = (mx == 0.0f) ? 0.0f : __fdividef(mn, mx);
    float t2 = t * t;
    float Lr = __logf(mx) + 0.5f * __logf(1.0f + t2);
    float p = t * (0.99997726f + t2 * (-0.33262347f + t2 * (0.19354346f +
              t2 * (-0.11643287f + t2 * (0.05265332f + t2 * (-0.01172120f))))));
    float r = (ay > ax) ? (PI_2_F - p) : p;
    if (__float_as_uint(z.re) & 0x80000000u)   // re negative or -0
        r = PI_F - r;
    C2 o;
    o.re = Lr;
    o.im = copysignf(r, z.im);
    return o;
}

__device__ __forceinline__ C2 merge_gen(C2 u, C2 w) {
    C2 A = fast_clog(u);
    C2 B = fast_clog(w);
    return cexp_mul_san(A.re, A.im, B.re, B.im);
}

// merge of two purely-real inputs (im == +0): clog degenerates.
__device__ __forceinline__ C2 merge_real(float lu, float rv) {
    float Ar = __logf(fabsf(lu));
    float Ai = (__float_as_uint(lu) >> 31) ? PI_F : 0.0f;
    float Br = __logf(fabsf(rv));
    float Bi = (__float_as_uint(rv) >> 31) ? PI_F : 0.0f;
    return cexp_mul_san(Ar, Ai, Br, Bi);
}

// (g0 + g1*x) + g2*val — reduced form, signed-zero-exact imag laundering.
__device__ __forceinline__ C2 affine(float g0, float g1, float g2,
                                     float xv, C2 val) {
    C2 r;
    r.re = __fmaf_rn(g2, val.re, __fmaf_rn(g1, xv, g0));
    r.im = __fmaf_rn(g2, val.im, 0.0f);
    return r;
}

// one gated merge from a float2-triple gate pointer
__device__ __forceinline__ C2 gated_merge(const float2* gp, float xv,
                                          C2 lft, C2 rgt) {
    float2 D0 = __ldg(gp);
    float2 D1 = __ldg(gp + 1);
    float2 D2 = __ldg(gp + 2);
    C2 a = affine(D0.x, D0.y, D1.x, xv, lft);
    C2 b = affine(D1.y, D2.x, D2.y, xv, rgt);
    return merge_gen(a, b);
}

__global__ void __launch_bounds__(64)
eml_tree_kernel(const float* __restrict__ x,
                const float* __restrict__ leaf,   // [1024][2]
                const float* __restrict__ gate,   // [1023][2][3]
                float* __restrict__ out,
                int batch, int write_imag) {
    int tid  = blockIdx.x * blockDim.x + threadIdx.x;
    int elem = tid >> 2;          // batch element
    int qt   = tid & 3;           // quarter index within the tree
    if (elem >= batch) return;

    const float xv = __ldg(x + elem);
    const float4* leaf4 = (const float4*)leaf;
    const float4* gate4 = (const float4*)gate;
    const float2* gate2 = (const float2*)gate;

    const int qbase = qt << 6;     // 64 quad-iterations per quarter

    C2 pend[9];                    // loop-heights 2..8
    C2 v; v.re = 0.0f; v.im = 0.0f;

    #pragma unroll 1
    for (int ql = 0; ql < 64; ++ql) {
        int q = qbase + ql;        // global quad index (leaf-pairs 2q, 2q+1)

        // ---- two level-0 merges, purely real ----
        float4 LA = __ldg(leaf4 + 2 * q);
        float4 LB = __ldg(leaf4 + 2 * q + 1);
        float4 G0 = __ldg(gate4 + 3 * q);
        float4 G1 = __ldg(gate4 + 3 * q + 1);
        float4 G2 = __ldg(gate4 + 3 * q + 2);

        float u0 = __fmaf_rn(LA.y, xv, LA.x);
        float u1 = __fmaf_rn(LA.w, xv, LA.z);
        float lu0 = __fmaf_rn(G0.z, u0, __fmaf_rn(G0.y, xv, G0.x));
        float rv0 = __fmaf_rn(G1.y, u1, __fmaf_rn(G1.x, xv, G0.w));
        C2 v1 = merge_real(lu0, rv0);

        float u2 = __fmaf_rn(LB.y, xv, LB.x);
        float u3 = __fmaf_rn(LB.w, xv, LB.z);
        float lu1 = __fmaf_rn(G2.x, u2, __fmaf_rn(G1.w, xv, G1.z));
        float rv1 = __fmaf_rn(G2.w, u3, __fmaf_rn(G2.z, xv, G2.y));
        C2 v2 = merge_real(lu1, rv1);

        // ---- static height-2 merge: gate node 512+q ----
        v = gated_merge(gate2 + 3 * (512 + q), xv, v1, v2);

        // ---- dynamic merges: one per trailing zero of (ql+1), own subtree ----
        int n = __ffs(ql + 1) - 1;
        int h = 2;
        #pragma unroll 1
        for (int j = 0; j < n; ++j, ++h) {
            int gidx = N_LEAVES - (N_LEAVES >> h) + (q >> (h - 1));
            v = gated_merge(gate2 + 3 * gidx, xv, pend[h], v);
        }
        pend[h] = v;               // last iter: pend[8] = height-8 quarter-root
    }

    // ---- height-8 merge across quarter pairs (gate 1020 + (t>>1)) ----
    {
        float pr = __shfl_xor_sync(0xffffffffu, v.re, 1);
        float pi = __shfl_xor_sync(0xffffffffu, v.im, 1);
        C2 lft, rgt;
        if ((qt & 1) == 0) { lft = v; rgt.re = pr; rgt.im = pi; }
        else               { lft.re = pr; lft.im = pi; rgt = v; }
        v = gated_merge(gate2 + 3 * (1020 + (qt >> 1)), xv, lft, rgt);
    }

    // ---- height-9 root merge across halves (gate 1022) ----
    {
        float pr = __shfl_xor_sync(0xffffffffu, v.re, 2);
        float pi = __shfl_xor_sync(0xffffffffu, v.im, 2);
        C2 lft, rgt;
        if ((qt & 2) == 0) { lft = v; rgt.re = pr; rgt.im = pi; }
        else               { lft.re = pr; lft.im = pi; rgt = v; }
        v = gated_merge(gate2 + 3 * 1022, xv, lft, rgt);
    }

    // PLANAR output (PROVEN): quarter 0 writes.
    if (qt == 0) {
        out[elem] = v.re;
        if (write_imag)
            out[batch + elem] = v.im;
    }
}

extern "C" void kernel_launch(void* const* d_in, const int* in_sizes, int n_in,
                              void* d_out, int out_size) {
    // Map inputs by unique element counts: x=65536, leaf=2048, gate=6138
    const float* x = nullptr;
    const float* leaf = nullptr;
    const float* gate = nullptr;
    int batch = 0;
    for (int i = 0; i < n_in; ++i) {
        if (in_sizes[i] == N_LEAVES * 2)        leaf = (const float*)d_in[i];
        else if (in_sizes[i] == N_INTERNAL * 6) gate = (const float*)d_in[i];
        else { x = (const float*)d_in[i]; batch = in_sizes[i]; }
    }

    int write_imag = (out_size >= 2 * batch) ? 1 : 0;

    int threads = 64;
    long total = 4L * batch;                       // 4 threads per element
    int blocks = (int)((total + threads - 1) / threads);
    eml_tree_kernel<<<blocks, threads>>>(x, leaf, gate, (float*)d_out,
                                         batch, write_imag);
}

// round 13
// speedup vs baseline: 1.5871x; 1.5871x over previous
#include <cuda_runtime.h>
#include <cuda_bf16.h>
#include <math.h>

// EMLTree1DLinear — planar output (PROVEN), 4-threads/element, WARP-PER-QUARTER.
// R12 regression diagnosed: quarter-per-lane made every param LDG touch 4
// cache lines (L1 wavefront bound, 80.7%). This round transposes the mapping:
// lane = element, warp = quarter -> all param loads are warp-uniform L1
// broadcasts again (R9-style), occupancy stays at 55 warps/SM. Cross-quarter
// merges via smem + 2 barriers, computed redundantly on both warp pairs with
// warp-uniform gate indices. Arithmetic bit-identical to R11/R12.

#define N_LEAVES   1024
#define N_INTERNAL 1023
#define CLAMP_F    1000000.0f
#define PI_F       3.14159265358979323846f
#define PI_2_F     1.57079632679489661923f

struct C2 { float re, im; };

__device__ __forceinline__ float san1(float v) {
    return (v != v) ? 0.0f : fminf(fmaxf(v, -CLAMP_F), CLAMP_F);
}

// sanitize(cexp(A*B)) — strict _rn complex mul keeps signed zeros / inf*0=NaN
__device__ __forceinline__ C2 cexp_mul_san(float Ar, float Ai, float Br, float Bi) {
    float mr = __fsub_rn(__fmul_rn(Ar, Br), __fmul_rn(Ai, Bi));
    float mi = __fadd_rn(__fmul_rn(Ar, Bi), __fmul_rn(Ai, Br));
    float e = __expf(mr);
    float s, c;
    __sincosf(mi, &s, &c);
    C2 w;
    w.re = san1(__fmul_rn(e, c));
    w.im = san1(__fmul_rn(e, s));
    return w;
}

// complex log, branch-cut exact (PROVEN): Lr = log|z| scaled-hypot,
// Li = atan2(im, re) via shared divide + deg-11 minimax.
__device__ __forceinline__ C2 fast_clog(C2 z) {
    float ax = fabsf(z.re), ay = fabsf(z.im);
    float mx = fmaxf(ax, ay);
    float mn = fminf(ax, ay);
    float t  = (mx == 0.0f) ? 0.0f : __fdividef(mn, mx);
    float t2 = t * t;
    float Lr = __logf(mx) + 0.5f * __logf(1.0f + t2);
    float p = t * (0.99997726f + t2 * (-0.33262347f + t2 * (0.19354346f +
              t2 * (-0.11643287f + t2 * (0.05265332f + t2 * (-0.01172120f))))));
    float r = (ay > ax) ? (PI_2_F - p) : p;
    if (__float_as_uint(z.re) & 0x80000000u)   // re negative or -0
        r = PI_F - r;
    C2 o;
    o.re = Lr;
    o.im = copysignf(r, z.im);
    return o;
}

__device__ __forceinline__ C2 merge_gen(C2 u, C2 w) {
    C2 A = fast_clog(u);
    C2 B = fast_clog(w);
    return cexp_mul_san(A.re, A.im, B.re, B.im);
}

// merge of two purely-real inputs (im == +0): clog degenerates.
__device__ __forceinline__ C2 merge_real(float lu, float rv) {
    float Ar = __logf(fabsf(lu));
    float Ai = (__float_as_uint(lu) >> 31) ? PI_F : 0.0f;
    float Br = __logf(fabsf(rv));
    float Bi = (__float_as_uint(rv) >> 31) ? PI_F : 0.0f;
    return cexp_mul_san(Ar, Ai, Br, Bi);
}

// (g0 + g1*x) + g2*val — reduced form, signed-zero-exact imag laundering.
__device__ __forceinline__ C2 affine(float g0, float g1, float g2,
                                     float xv, C2 val) {
    C2 r;
    r.re = __fmaf_rn(g2, val.re, __fmaf_rn(g1, xv, g0));
    r.im = __fmaf_rn(g2, val.im, 0.0f);
    return r;
}

// one gated merge from a float2-triple gate pointer (warp-uniform gp)
__device__ __forceinline__ C2 gated_merge(const float2* gp, float xv,
                                          C2 lft, C2 rgt) {
    float2 D0 = __ldg(gp);
    float2 D1 = __ldg(gp + 1);
    float2 D2 = __ldg(gp + 2);
    C2 a = affine(D0.x, D0.y, D1.x, xv, lft);
    C2 b = affine(D1.y, D2.x, D2.y, xv, rgt);
    return merge_gen(a, b);
}

__global__ void __launch_bounds__(128)
eml_tree_kernel(const float* __restrict__ x,
                const float* __restrict__ leaf,   // [1024][2]
                const float* __restrict__ gate,   // [1023][2][3]
                float* __restrict__ out,
                int batch, int write_imag) {
    __shared__ float sre[128], sim[128];

    int lane = threadIdx.x & 31;
    int qt   = threadIdx.x >> 5;            // warp = quarter 0..3
    int elem = blockIdx.x * 32 + lane;      // lane = element
    int e    = (elem < batch) ? elem : (batch - 1);

    const float xv = __ldg(x + e);
    const float4* leaf4 = (const float4*)leaf;
    const float4* gate4 = (const float4*)gate;
    const float2* gate2 = (const float2*)gate;

    const int qbase = qt << 6;     // 64 quad-iterations per quarter

    C2 pend[9];                    // loop-heights 2..8
    C2 v; v.re = 0.0f; v.im = 0.0f;

    #pragma unroll 1
    for (int ql = 0; ql < 64; ++ql) {
        int q = qbase + ql;        // global quad index (leaf-pairs 2q, 2q+1)

        // ---- two level-0 merges, purely real (all loads warp-uniform) ----
        float4 LA = __ldg(leaf4 + 2 * q);
        float4 LB = __ldg(leaf4 + 2 * q + 1);
        float4 G0 = __ldg(gate4 + 3 * q);
        float4 G1 = __ldg(gate4 + 3 * q + 1);
        float4 G2 = __ldg(gate4 + 3 * q + 2);

        float u0 = __fmaf_rn(LA.y, xv, LA.x);
        float u1 = __fmaf_rn(LA.w, xv, LA.z);
        float lu0 = __fmaf_rn(G0.z, u0, __fmaf_rn(G0.y, xv, G0.x));
        float rv0 = __fmaf_rn(G1.y, u1, __fmaf_rn(G1.x, xv, G0.w));
        C2 v1 = merge_real(lu0, rv0);

        float u2 = __fmaf_rn(LB.y, xv, LB.x);
        float u3 = __fmaf_rn(LB.w, xv, LB.z);
        float lu1 = __fmaf_rn(G2.x, u2, __fmaf_rn(G1.w, xv, G1.z));
        float rv1 = __fmaf_rn(G2.w, u3, __fmaf_rn(G2.z, xv, G2.y));
        C2 v2 = merge_real(lu1, rv1);

        // ---- static height-2 merge: gate node 512+q ----
        v = gated_merge(gate2 + 3 * (512 + q), xv, v1, v2);

        // ---- dynamic merges: one per trailing zero of (ql+1), own subtree ----
        int n = __ffs(ql + 1) - 1;
        int h = 2;
        #pragma unroll 1
        for (int j = 0; j < n; ++j, ++h) {
            int gidx = N_LEAVES - (N_LEAVES >> h) + (q >> (h - 1));
            v = gated_merge(gate2 + 3 * gidx, xv, pend[h], v);
        }
        pend[h] = v;               // last iter: pend[8] = height-8 quarter-root
    }

    // ---- height-8 merge across warp pairs (gate 1020 + (qt>>1)) ----
    sre[threadIdx.x] = v.re;
    sim[threadIdx.x] = v.im;
    __syncthreads();
    {
        int pidx = ((qt ^ 1) << 5) | lane;
        C2 part; part.re = sre[pidx]; part.im = sim[pidx];
        C2 lft, rgt;
        if ((qt & 1) == 0) { lft = v; rgt = part; }
        else               { lft = part; rgt = v; }
        v = gated_merge(gate2 + 3 * (1020 + (qt >> 1)), xv, lft, rgt);
    }
    __syncthreads();

    // ---- height-9 root merge across half pairs (gate 1022) ----
    sre[threadIdx.x] = v.re;
    sim[threadIdx.x] = v.im;
    __syncthreads();
    {
        int pidx = ((qt ^ 2) << 5) | lane;
        C2 part; part.re = sre[pidx]; part.im = sim[pidx];
        C2 lft, rgt;
        if ((qt & 2) == 0) { lft = v; rgt = part; }
        else               { lft = part; rgt = v; }
        v = gated_merge(gate2 + 3 * 1022, xv, lft, rgt);
    }

    // PLANAR output (PROVEN): warp 0 writes, lane-coalesced.
    if (qt == 0 && elem < batch) {
        out[elem] = v.re;
        if (write_imag)
            out[batch + elem] = v.im;
    }
}

extern "C" void kernel_launch(void* const* d_in, const int* in_sizes, int n_in,
                              void* d_out, int out_size) {
    // Map inputs by unique element counts: x=65536, leaf=2048, gate=6138
    const float* x = nullptr;
    const float* leaf = nullptr;
    const float* gate = nullptr;
    int batch = 0;
    for (int i = 0; i < n_in; ++i) {
        if (in_sizes[i] == N_LEAVES * 2)        leaf = (const float*)d_in[i];
        else if (in_sizes[i] == N_INTERNAL * 6) gate = (const float*)d_in[i];
        else { x = (const float*)d_in[i]; batch = in_sizes[i]; }
    }

    int write_imag = (out_size >= 2 * batch) ? 1 : 0;

    int threads = 128;                       // 4 warps = 4 quarters
    int blocks = (batch + 31) / 32;          // 32 elements per block
    eml_tree_kernel<<<blocks, threads>>>(x, leaf, gate, (float*)d_out,
                                         batch, write_imag);
}

// round 17
// speedup vs baseline: 1.7263x; 1.0877x over previous
#include <cuda_runtime.h>
#include <cuda_bf16.h>
#include <math.h>

// EMLTree1DLinear — planar output (PROVEN), 4-threads/element, WARP-PER-QUARTER
// (PROVEN R13). This round: cheaper clog magnitude. The sanitize clamp bounds
// every affine input to |z| <~ 1.4e6, so re^2+im^2 <= ~4e12 cannot overflow;
// underflow needs ~19-digit cancellation (prob ~0, and exact zero still maps
// to log(0) = -inf like the reference). So:
//     Lr = 0.5*__logf(fma(re,re, im*im))     (1 MUFU instead of 2, -6 instr)
// Angle path (divide + minimax atan + octant/sign logic) unchanged — it is
// the proven branch-cut/signed-zero-exact machinery.
// (Resubmission of the R16 kernel: that bench died at container level, the
// kernel itself was never measured.)

#define N_LEAVES   1024
#define N_INTERNAL 1023
#define CLAMP_F    1000000.0f
#define PI_F       3.14159265358979323846f
#define PI_2_F     1.57079632679489661923f

struct C2 { float re, im; };

__device__ __forceinline__ float san1(float v) {
    return (v != v) ? 0.0f : fminf(fmaxf(v, -CLAMP_F), CLAMP_F);
}

// sanitize(cexp(A*B)) — strict _rn complex mul keeps signed zeros / inf*0=NaN
__device__ __forceinline__ C2 cexp_mul_san(float Ar, float Ai, float Br, float Bi) {
    float mr = __fsub_rn(__fmul_rn(Ar, Br), __fmul_rn(Ai, Bi));
    float mi = __fadd_rn(__fmul_rn(Ar, Bi), __fmul_rn(Ai, Br));
    float e = __expf(mr);
    float s, c;
    __sincosf(mi, &s, &c);
    C2 w;
    w.re = san1(__fmul_rn(e, c));
    w.im = san1(__fmul_rn(e, s));
    return w;
}

// complex log, branch-cut exact (PROVEN angle path); squared-norm magnitude
// (safe: inputs clamp-bounded, no overflow; underflow band unreachable).
__device__ __forceinline__ C2 fast_clog(C2 z) {
    float ax = fabsf(z.re), ay = fabsf(z.im);
    float mx = fmaxf(ax, ay);
    float mn = fminf(ax, ay);
    float t  = __fdividef(mn, fmaxf(mx, 1e-45f));   // mx==0 -> t=0
    float t2 = t * t;
    float Lr = 0.5f * __logf(__fmaf_rn(z.re, z.re, __fmul_rn(z.im, z.im)));
    float p = t * (0.99997726f + t2 * (-0.33262347f + t2 * (0.19354346f +
              t2 * (-0.11643287f + t2 * (0.05265332f + t2 * (-0.01172120f))))));
    float r = (ay > ax) ? (PI_2_F - p) : p;
    if (__float_as_uint(z.re) & 0x80000000u)   // re negative or -0
        r = PI_F - r;
    C2 o;
    o.re = Lr;
    o.im = copysignf(r, z.im);
    return o;
}

__device__ __forceinline__ C2 merge_gen(C2 u, C2 w) {
    C2 A = fast_clog(u);
    C2 B = fast_clog(w);
    return cexp_mul_san(A.re, A.im, B.re, B.im);
}

// merge of two purely-real inputs (im == +0): clog degenerates.
__device__ __forceinline__ C2 merge_real(float lu, float rv) {
    float Ar = __logf(fabsf(lu));
    float Ai = (__float_as_uint(lu) >> 31) ? PI_F : 0.0f;
    float Br = __logf(fabsf(rv));
    float Bi = (__float_as_uint(rv) >> 31) ? PI_F : 0.0f;
    return cexp_mul_san(Ar, Ai, Br, Bi);
}

// (g0 + g1*x) + g2*val — reduced form, signed-zero-exact imag laundering.
__device__ __forceinline__ C2 affine(float g0, float g1, float g2,
                                     float xv, C2 val) {
    C2 r;
    r.re = __fmaf_rn(g2, val.re, __fmaf_rn(g1, xv, g0));
    r.im = __fmaf_rn(g2, val.im, 0.0f);
    return r;
}

// one gated merge from a float2-triple gate pointer (warp-uniform gp)
__device__ __forceinline__ C2 gated_merge(const float2* gp, float xv,
                                          C2 lft, C2 rgt) {
    float2 D0 = __ldg(gp);
    float2 D1 = __ldg(gp + 1);
    float2 D2 = __ldg(gp + 2);
    C2 a = affine(D0.x, D0.y, D1.x, xv, lft);
    C2 b = affine(D1.y, D2.x, D2.y, xv, rgt);
    return merge_gen(a, b);
}

__global__ void __launch_bounds__(128)
eml_tree_kernel(const float* __restrict__ x,
                const float* __restrict__ leaf,   // [1024][2]
                const float* __restrict__ gate,   // [1023][2][3]
                float* __restrict__ out,
                int batch, int write_imag) {
    __shared__ float sre[128], sim[128];

    int lane = threadIdx.x & 31;
    int qt   = threadIdx.x >> 5;            // warp = quarter 0..3
    int elem = blockIdx.x * 32 + lane;      // lane = element
    int e    = (elem < batch) ? elem : (batch - 1);

    const float xv = __ldg(x + e);
    const float4* leaf4 = (const float4*)leaf;
    const float4* gate4 = (const float4*)gate;
    const float2* gate2 = (const float2*)gate;

    const int qbase = qt << 6;     // 64 quad-iterations per quarter

    C2 pend[9];                    // loop-heights 2..8
    C2 v; v.re = 0.0f; v.im = 0.0f;

    #pragma unroll 1
    for (int ql = 0; ql < 64; ++ql) {
        int q = qbase + ql;        // global quad index (leaf-pairs 2q, 2q+1)

        // ---- two level-0 merges, purely real (all loads warp-uniform) ----
        float4 LA = __ldg(leaf4 + 2 * q);
        float4 LB = __ldg(leaf4 + 2 * q + 1);
        float4 G0 = __ldg(gate4 + 3 * q);
        float4 G1 = __ldg(gate4 + 3 * q + 1);
        float4 G2 = __ldg(gate4 + 3 * q + 2);

        float u0 = __fmaf_rn(LA.y, xv, LA.x);
        float u1 = __fmaf_rn(LA.w, xv, LA.z);
        float lu0 = __fmaf_rn(G0.z, u0, __fmaf_rn(G0.y, xv, G0.x));
        float rv0 = __fmaf_rn(G1.y, u1, __fmaf_rn(G1.x, xv, G0.w));
        C2 v1 = merge_real(lu0, rv0);

        float u2 = __fmaf_rn(LB.y, xv, LB.x);
        float u3 = __fmaf_rn(LB.w, xv, LB.z);
        float lu1 = __fmaf_rn(G2.x, u2, __fmaf_rn(G1.w, xv, G1.z));
        float rv1 = __fmaf_rn(G2.w, u3, __fmaf_rn(G2.z, xv, G2.y));
        C2 v2 = merge_real(lu1, rv1);

        // ---- static height-2 merge: gate node 512+q ----
        v = gated_merge(gate2 + 3 * (512 + q), xv, v1, v2);

        // ---- dynamic merges: one per trailing zero of (ql+1), own subtree ----
        int n = __ffs(ql + 1) - 1;
        int h = 2;
        #pragma unroll 1
        for (int j = 0; j < n; ++j, ++h) {
            int gidx = N_LEAVES - (N_LEAVES >> h) + (q >> (h - 1));
            v = gated_merge(gate2 + 3 * gidx, xv, pend[h], v);
        }
        pend[h] = v;               // last iter: pend[8] = height-8 quarter-root
    }

    // ---- height-8 merge across warp pairs (gate 1020 + (qt>>1)) ----
    sre[threadIdx.x] = v.re;
    sim[threadIdx.x] = v.im;
    __syncthreads();
    {
        int pidx = ((qt ^ 1) << 5) | lane;
        C2 part; part.re = sre[pidx]; part.im = sim[pidx];
        C2 lft, rgt;
        if ((qt & 1) == 0) { lft = v; rgt = part; }
        else               { lft = part; rgt = v; }
        v = gated_merge(gate2 + 3 * (1020 + (qt >> 1)), xv, lft, rgt);
    }
    __syncthreads();

    // ---- height-9 root merge across half pairs (gate 1022) ----
    sre[threadIdx.x] = v.re;
    sim[threadIdx.x] = v.im;
    __syncthreads();
    {
        int pidx = ((qt ^ 2) << 5) | lane;
        C2 part; part.re = sre[pidx]; part.im = sim[pidx];
        C2 lft, rgt;
        if ((qt & 2) == 0) { lft = v; rgt = part; }
        else               { lft = part; rgt = v; }
        v = gated_merge(gate2 + 3 * 1022, xv, lft, rgt);
    }

    // PLANAR output (PROVEN): warp 0 writes, lane-coalesced.
    if (qt == 0 && elem < batch) {
        out[elem] = v.re;
        if (write_imag)
            out[batch + elem] = v.im;
    }
}

extern "C" void kernel_launch(void* const* d_in, const int* in_sizes, int n_in,
                              void* d_out, int out_size) {
    // Map inputs by unique element counts: x=65536, leaf=2048, gate=6138
    const float* x = nullptr;
    const float* leaf = nullptr;
    const float* gate = nullptr;
    int batch = 0;
    for (int i = 0; i < n_in; ++i) {
        if (in_sizes[i] == N_LEAVES * 2)        leaf = (const float*)d_in[i];
        else if (in_sizes[i] == N_INTERNAL * 6) gate = (const float*)d_in[i];
        else { x = (const float*)d_in[i]; batch = in_sizes[i]; }
    }

    int write_imag = (out_size >= 2 * batch) ? 1 : 0;

    int threads = 128;                       // 4 warps = 4 quarters
    int blocks = (batch + 31) / 32;          // 32 elements per block
    eml_tree_kernel<<<blocks, threads>>>(x, leaf, gate, (float*)d_out,
                                         batch, write_imag);
}